// round 1
// baseline (speedup 1.0000x reference)
#include <cuda_runtime.h>
#include <cuda_bf16.h>
#include <math.h>

// ---------------------------------------------------------------------------
// Problem constants
// ---------------------------------------------------------------------------
#define Hh   2048
#define Kk   16
#define NQ   18          // K + 2
#define NHh  4
#define HD   512         // H / NH
#define FFN  4096        // 2*H
#define MAXE 128
#define Bb   4
#define Ss   4096
#define QH   72          // NQ * NH
#define EPSf 1e-6f

// Output layout (float32, concatenated in return order)
constexpr long OFF_MEM  = 0;                       // (4,16,2048) = 131072
constexpr long OFF_PRI  = 131072;                  // (4,16)      = 64
constexpr long OFF_CONF = 131136;                  // (4,)        = 4
constexpr long OFF_VAL  = 131140;                  // (4,)        = 4
constexpr long OFF_ENT  = 131144;                  // (128,2048)  = 262144
constexpr long OFF_NPRI = 393288;                  // (128,)      = 128

// Scratch arena offsets (floats). [0, ZERO_END) is zeroed each call (atomic targets).
constexpr long OFF_QPROJ   = 0;         // 18*2048   = 36864
constexpr long OFF_OUTATTN = 36864;     // 72*2048   = 147456
constexpr long OFF_EXTR    = 184320;    // 72*2048   = 147456
constexpr long OFF_GBUF    = 331776;    // 64*4096   = 262144
constexpr long OFF_UBUF    = 593920;    // 64*4096   = 262144
constexpr long OFF_FBUF    = 856064;    // 64*2048   = 131072
constexpr long OFF_H1PRE   = 987136;    // 4*2048    = 8192
constexpr long OFF_H2PRE   = 995328;    // 4*512     = 2048
constexpr long OFF_SCORES  = 997376;    // 16384*72  = 1179648
constexpr long OFF_CTX     = 2177024;   // 4*72*2048 = 589824
constexpr long ZERO_END    = 2766848;
constexpr long OFF_AMAT    = 2766848;   // 72*2048   = 147456
constexpr long OFF_ATTN    = 2914304;   // 4*72*4096 = 1179648
constexpr long OFF_XN      = 4093952;   // 64*2048   = 131072
constexpr long OFF_TBUF    = 4225024;   // 64*4096   = 262144
constexpr long OFF_VI      = 4487168;   // 4*4096    = 16384
constexpr long OFF_H1      = 4503552;   // 4*2048    = 8192
constexpr long OFF_H2      = 4511744;   // 4*512     = 2048
constexpr long SCRATCH_SZ  = 4513792;

__device__ float g_scratch[SCRATCH_SZ];

// ---------------------------------------------------------------------------
// Generic tiled GEMM:  C[M,N] (+)= alpha * A[M,K] * op(B)
//   TRANSB=true : B stored [N,K]  (C = A @ B^T)
//   TRANSB=false: B stored [K,N]  (C = A @ B)
// grid: x = n-tile, y = m-tile, z = batch*ksplit. If ksplit>1, atomicAdd into C
// (C must be pre-zeroed). lda/ldb/ldc are row strides; aB/bB/cB batch offsets.
// ---------------------------------------------------------------------------
template<int TM, int TN, bool TRANSB>
__global__ __launch_bounds__(256)
void gemm_k(const float* __restrict__ A, const float* __restrict__ B,
            float* __restrict__ C,
            int M, int N, int K, int lda, int ldb, int ldc,
            long aB, long bB, long cB, int ksplit, float alpha)
{
    constexpr int BM = 16 * TM, BN = 16 * TN, BK = 32;
    __shared__ float As[BK][BM + 1];
    __shared__ float Bs[BK][BN + 1];

    const int tid   = threadIdx.x;
    const int batch = blockIdx.z / ksplit;
    const int ks    = blockIdx.z % ksplit;
    A += batch * aB; B += batch * bB; C += batch * cB;

    const int kLen = K / ksplit;
    const int k0   = ks * kLen;
    const int m0   = blockIdx.y * BM;
    const int n0   = blockIdx.x * BN;
    const int tx   = tid & 15, ty = tid >> 4;

    float acc[TM][TN];
#pragma unroll
    for (int i = 0; i < TM; i++)
#pragma unroll
        for (int j = 0; j < TN; j++) acc[i][j] = 0.f;

    for (int kt = 0; kt < kLen; kt += BK) {
        // A tile (BM x BK), stored transposed As[k][m]
#pragma unroll
        for (int idx = tid; idx < BM * BK; idx += 256) {
            int r = idx >> 5, c = idx & 31;
            int m = m0 + r;
            As[c][r] = (m < M) ? A[(long)m * lda + (k0 + kt + c)] : 0.f;
        }
        if (TRANSB) {
#pragma unroll
            for (int idx = tid; idx < BN * BK; idx += 256) {
                int r = idx >> 5, c = idx & 31;
                int n = n0 + r;
                Bs[c][r] = (n < N) ? B[(long)n * ldb + (k0 + kt + c)] : 0.f;
            }
        } else {
#pragma unroll
            for (int idx = tid; idx < BK * BN; idx += 256) {
                int r = idx / BN, c = idx % BN;
                int n = n0 + c;
                Bs[r][c] = (n < N) ? B[(long)(k0 + kt + r) * ldb + n] : 0.f;
            }
        }
        __syncthreads();
#pragma unroll
        for (int kk = 0; kk < BK; kk++) {
            float a[TM], b[TN];
#pragma unroll
            for (int i = 0; i < TM; i++) a[i] = As[kk][ty * TM + i];
#pragma unroll
            for (int j = 0; j < TN; j++) b[j] = Bs[kk][tx * TN + j];
#pragma unroll
            for (int i = 0; i < TM; i++)
#pragma unroll
                for (int j = 0; j < TN; j++)
                    acc[i][j] = fmaf(a[i], b[j], acc[i][j]);
        }
        __syncthreads();
    }

#pragma unroll
    for (int i = 0; i < TM; i++) {
        int m = m0 + ty * TM + i;
        if (m >= M) continue;
#pragma unroll
        for (int j = 0; j < TN; j++) {
            int n = n0 + tx * TN + j;
            if (n >= N) continue;
            float v = alpha * acc[i][j];
            if (ksplit > 1) atomicAdd(&C[(long)m * ldc + n], v);
            else            C[(long)m * ldc + n] = v;
        }
    }
}

// ---------------------------------------------------------------------------
// Elementwise / reduction kernels
// ---------------------------------------------------------------------------
__global__ void zero4_k(float4* p, int n4)
{
    int i = blockIdx.x * blockDim.x + threadIdx.x;
    if (i < n4) p[i] = make_float4(0.f, 0.f, 0.f, 0.f);
}

__device__ __forceinline__ float blockReduceSum(float v, float* sm)
{
    int t = threadIdx.x;
    __syncthreads();
    sm[t] = v; __syncthreads();
    for (int o = blockDim.x >> 1; o > 0; o >>= 1) {
        if (t < o) sm[t] += sm[t + o];
        __syncthreads();
    }
    return sm[0];
}

__device__ __forceinline__ float blockReduceMax(float v, float* sm)
{
    int t = threadIdx.x;
    __syncthreads();
    sm[t] = v; __syncthreads();
    for (int o = blockDim.x >> 1; o > 0; o >>= 1) {
        if (t < o) sm[t] = fmaxf(sm[t], sm[t + o]);
        __syncthreads();
    }
    return sm[0];
}

// softmax over s for each (b, qh); reads scores_t[s][72] (strided), writes
// attn[b][qh][s] row-major.
__global__ void softmax_k()
{
    __shared__ float sm[256];
    int b  = blockIdx.x / QH;
    int qh = blockIdx.x % QH;
    const float* src = g_scratch + OFF_SCORES + (long)b * Ss * QH + qh;
    float* dst       = g_scratch + OFF_ATTN   + ((long)b * QH + qh) * Ss;
    int t = threadIdx.x;

    float mx = -1e30f;
    for (int s = t; s < Ss; s += 256) mx = fmaxf(mx, src[(long)s * QH]);
    mx = blockReduceMax(mx, sm);

    float sum = 0.f;
    for (int s = t; s < Ss; s += 256) {
        float e = expf(src[(long)s * QH] - mx);
        dst[s] = e;
        sum += e;
    }
    sum = blockReduceSum(sum, sm);
    float inv = 1.f / sum;
    for (int s = t; s < Ss; s += 256) dst[s] *= inv;
}

// RMSNorm of extracted[:, :16] -> xn
__global__ void rms_k(const float* __restrict__ ln_w)
{
    __shared__ float sm[256];
    int b = blockIdx.x >> 4, q = blockIdx.x & 15;
    const float* x = g_scratch + OFF_EXTR + (long)(b * NQ + q) * Hh;
    float* xo      = g_scratch + OFF_XN   + (long)(b * Kk + q) * Hh;
    int t = threadIdx.x;
    float s = 0.f;
    for (int j = t; j < Hh; j += 256) { float v = x[j]; s += v * v; }
    s = blockReduceSum(s, sm);
    float scale = rsqrtf(s / (float)Hh + EPSf);
    for (int j = t; j < Hh; j += 256) xo[j] = x[j] * scale * ln_w[j];
}

__global__ void silu_mul_k(int n)
{
    int i = blockIdx.x * blockDim.x + threadIdx.x;
    if (i < n) {
        float g = g_scratch[OFF_GBUF + i];
        float u = g_scratch[OFF_UBUF + i];
        float s = 1.f / (1.f + expf(-g));
        g_scratch[OFF_TBUF + i] = g * s * u;
    }
}

__global__ void bias_silu_k(long pre_off, const float* __restrict__ bias,
                            long out_off, int n, int bdim)
{
    int i = blockIdx.x * blockDim.x + threadIdx.x;
    if (i < n) {
        float v = g_scratch[pre_off + i] + bias[i % bdim];
        float s = 1.f / (1.f + expf(-v));
        g_scratch[out_off + i] = v * s;
    }
}

// memory = memory_raw + ffn (written to OUT), priority = sigmoid(memory.Wp + bp)
__global__ void mem_pri_k(const float* __restrict__ Wp,
                          const float* __restrict__ bp,
                          float* __restrict__ OUT)
{
    __shared__ float sm[256];
    int b = blockIdx.x >> 4, i = blockIdx.x & 15;
    const float* ex = g_scratch + OFF_EXTR + (long)(b * NQ + i) * Hh;
    const float* fb = g_scratch + OFF_FBUF + (long)(b * Kk + i) * Hh;
    float* mo = OUT + OFF_MEM + (long)(b * Kk + i) * Hh;
    int t = threadIdx.x;
    float dot = 0.f;
    for (int j = t; j < Hh; j += 256) {
        float m = ex[j] + fb[j];
        mo[j] = m;
        dot += m * Wp[j];
    }
    dot = blockReduceSum(dot, sm);
    if (t == 0) OUT[OFF_PRI + b * Kk + i] = 1.f / (1.f + expf(-(dot + bp[0])));
}

__global__ void conf_k(const float* __restrict__ Wh,
                       const float* __restrict__ bh,
                       float* __restrict__ OUT)
{
    __shared__ float sm[256];
    int b = blockIdx.x;
    const float* cv = g_scratch + OFF_EXTR + (long)(b * NQ + Kk) * Hh;
    int t = threadIdx.x;
    float dot = 0.f;
    for (int j = t; j < Hh; j += 256) dot += cv[j] * Wh[j];
    dot = blockReduceSum(dot, sm);
    if (t == 0) OUT[OFF_CONF + b] = 1.f / (1.f + expf(-(dot + bh[0])));
}

__global__ void vi_k(const float* __restrict__ hidden)
{
    int b = blockIdx.x;
    const float* vv = g_scratch + OFF_EXTR + (long)(b * NQ + Kk + 1) * Hh;
    const float* hl = hidden + ((long)b * Ss + (Ss - 1)) * Hh;
    float* vi = g_scratch + OFF_VI + (long)b * (2 * Hh);
    for (int j = threadIdx.x; j < 2 * Hh; j += 256)
        vi[j] = (j < Hh) ? vv[j] : hl[j - Hh];
}

__global__ void value_k(const float* __restrict__ V3,
                        const float* __restrict__ b3,
                        float* __restrict__ OUT)
{
    __shared__ float sm[256];
    int b = blockIdx.x;
    const float* h2 = g_scratch + OFF_H2 + (long)b * (Hh / 4);
    int t = threadIdx.x;
    float dot = 0.f;
    for (int j = t; j < Hh / 4; j += 256) dot += h2[j] * V3[j];
    dot = blockReduceSum(dot, sm);
    if (t == 0) OUT[OFF_VAL + b] = dot + b3[0];
}

__global__ void copy_ent_k(const float* __restrict__ src, float* __restrict__ OUT)
{
    long i = (long)blockIdx.x * blockDim.x + threadIdx.x;
    if (i < (long)MAXE * Hh) OUT[OFF_ENT + i] = src[i];
}

// Sequential buffer-update scan (matches jax.lax.scan with first-index argmin).
__global__ void scan_k(const float* __restrict__ buf_pri, float* __restrict__ OUT)
{
    __shared__ float pr[MAXE];
    __shared__ float sval[MAXE];
    __shared__ int   sidx[MAXE];
    int t = threadIdx.x;           // 128 threads
    pr[t] = buf_pri[t];
    __syncthreads();

    for (int i = 0; i < Kk; i++) {
        sval[t] = pr[t]; sidx[t] = t;
        __syncthreads();
        for (int o = MAXE >> 1; o > 0; o >>= 1) {
            if (t < o) {
                float v2 = sval[t + o]; int i2 = sidx[t + o];
                if (v2 < sval[t] || (v2 == sval[t] && i2 < sidx[t])) {
                    sval[t] = v2; sidx[t] = i2;
                }
            }
            __syncthreads();
        }
        int   idx  = sidx[0];
        float minv = sval[0];
        float p    = OUT[OFF_PRI + i];      // priority[0][i]
        if (p > minv) {
            for (int j = t; j < Hh; j += MAXE)
                OUT[OFF_ENT + (long)idx * Hh + j] = OUT[OFF_MEM + (long)i * Hh + j];
            if (t == 0) pr[idx] = p;
        }
        __syncthreads();
    }
    OUT[OFF_NPRI + t] = pr[t];
}

// ---------------------------------------------------------------------------
// Launch sequence
// ---------------------------------------------------------------------------
extern "C" void kernel_launch(void* const* d_in, const int* in_sizes, int n_in,
                              void* d_out, int out_size)
{
    const float* hidden  = (const float*)d_in[0];
    const float* bufent  = (const float*)d_in[1];
    const float* bufpri  = (const float*)d_in[2];
    const float* queries = (const float*)d_in[3];
    const float* Wq      = (const float*)d_in[4];
    const float* Wk      = (const float*)d_in[5];
    const float* Wv      = (const float*)d_in[6];
    const float* Wo      = (const float*)d_in[7];
    const float* ln_w    = (const float*)d_in[8];
    const float* Wgate   = (const float*)d_in[9];
    const float* Wup     = (const float*)d_in[10];
    const float* Wdown   = (const float*)d_in[11];
    const float* Wp      = (const float*)d_in[12];
    const float* bp      = (const float*)d_in[13];
    const float* Wh      = (const float*)d_in[14];
    const float* bh      = (const float*)d_in[15];
    const float* V1      = (const float*)d_in[16];
    const float* b1      = (const float*)d_in[17];
    const float* V2      = (const float*)d_in[18];
    const float* b2      = (const float*)d_in[19];
    const float* V3      = (const float*)d_in[20];
    const float* b3      = (const float*)d_in[21];
    float* OUT = (float*)d_out;

    float* scr = nullptr;
    cudaGetSymbolAddress((void**)&scr, g_scratch);

    const float inv_sqrt_hd = 0.044194173824159216f;   // 1/sqrt(512)

    // 0) zero split-K targets
    {
        int n4 = (int)(ZERO_END / 4);
        zero4_k<<<(n4 + 255) / 256, 256>>>((float4*)scr, n4);
    }

    // 1) q_proj = queries @ Wq^T : (18, 2048)
    gemm_k<4,4,true><<<dim3(32,1,4), 256>>>(queries, Wq, scr + OFF_QPROJ,
        18, 2048, 2048, 2048, 2048, 2048, 0, 0, 0, 4, 1.f);

    // 2) A[q*4+h, :] = q_proj[q, h*512:] @ Wk[h*512:, :] * 1/sqrt(HD)   (4 head batches)
    gemm_k<4,4,false><<<dim3(32,1,4), 256>>>(scr + OFF_QPROJ, Wk, scr + OFF_AMAT,
        18, 2048, 512, 2048, 2048, 4*2048,
        512, (long)512*2048, 2048, 1, inv_sqrt_hd);

    // 3) scores_t[s, qh] = hidden @ A^T : (16384, 72), split-K=2
    gemm_k<8,5,true><<<dim3(1,128,2), 256>>>(hidden, scr + OFF_AMAT, scr + OFF_SCORES,
        16384, QH, 2048, 2048, 2048, QH, 0, 0, 0, 2, 1.f);

    // 4) softmax over s -> attn[b][qh][s]
    softmax_k<<<Bb * QH, 256>>>();

    // 5) ctx[b][qh][n] = attn[b] @ hidden[b] : (72, 2048) x4 batches, split-K=2
    gemm_k<5,4,false><<<dim3(32,1,8), 256>>>(scr + OFF_ATTN, hidden, scr + OFF_CTX,
        QH, 2048, 4096, 4096, 2048, 2048,
        (long)QH*4096, (long)4096*2048, (long)QH*2048, 2, 1.f);

    // 6) out_attn[r, h*512+d] = ctx[r(head h)] @ Wv_h^T  (4 head batches, split-K=4)
    gemm_k<5,4,true><<<dim3(8,1,16), 256>>>(scr + OFF_CTX, Wv, scr + OFF_OUTATTN,
        QH, 512, 2048, 4*2048, 2048, 2048,
        2048, (long)512*2048, 512, 4, 1.f);

    // 7) extracted = out_attn @ Wo^T : (72, 2048), split-K=4
    gemm_k<5,4,true><<<dim3(32,1,4), 256>>>(scr + OFF_OUTATTN, Wo, scr + OFF_EXTR,
        QH, 2048, 2048, 2048, 2048, 2048, 0, 0, 0, 4, 1.f);

    // 8) RMSNorm -> xn (64, 2048)
    rms_k<<<64, 256>>>(ln_w);

    // 9) gate / up : (64, 4096), split-K=4
    gemm_k<4,4,true><<<dim3(64,1,4), 256>>>(scr + OFF_XN, Wgate, scr + OFF_GBUF,
        64, 4096, 2048, 2048, 2048, 4096, 0, 0, 0, 4, 1.f);
    gemm_k<4,4,true><<<dim3(64,1,4), 256>>>(scr + OFF_XN, Wup, scr + OFF_UBUF,
        64, 4096, 2048, 2048, 2048, 4096, 0, 0, 0, 4, 1.f);

    // 10) t = silu(gate) * up
    silu_mul_k<<<(64*4096 + 255) / 256, 256>>>(64 * 4096);

    // 11) ffn = t @ Wdown^T : (64, 2048), split-K=8
    gemm_k<4,4,true><<<dim3(32,1,8), 256>>>(scr + OFF_TBUF, Wdown, scr + OFF_FBUF,
        64, 2048, 4096, 4096, 4096, 2048, 0, 0, 0, 8, 1.f);

    // 12) memory (to OUT) + priority
    mem_pri_k<<<64, 256>>>(Wp, bp, OUT);

    // 13) confidence
    conf_k<<<4, 256>>>(Wh, bh, OUT);

    // 14) value head
    vi_k<<<4, 256>>>(hidden);
    gemm_k<4,4,true><<<dim3(32,1,8), 256>>>(scr + OFF_VI, V1, scr + OFF_H1PRE,
        4, 2048, 4096, 4096, 4096, 2048, 0, 0, 0, 8, 1.f);
    bias_silu_k<<<(4*2048 + 255) / 256, 256>>>(OFF_H1PRE, b1, OFF_H1, 4*2048, 2048);
    gemm_k<4,4,true><<<dim3(8,1,4), 256>>>(scr + OFF_H1, V2, scr + OFF_H2PRE,
        4, 512, 2048, 2048, 2048, 512, 0, 0, 0, 4, 1.f);
    bias_silu_k<<<(4*512 + 255) / 256, 256>>>(OFF_H2PRE, b2, OFF_H2, 4*512, 512);
    value_k<<<4, 256>>>(V3, b3, OUT);

    // 15) buffer update: copy entries, then sequential scan
    copy_ent_k<<<(MAXE*Hh + 255) / 256, 256>>>(bufent, OUT);
    scan_k<<<1, MAXE>>>(bufpri, OUT);
}

// round 2
// speedup vs baseline: 1.1025x; 1.1025x over previous
#include <cuda_runtime.h>
#include <cuda_bf16.h>
#include <math.h>

// ---------------------------------------------------------------------------
// Problem constants
// ---------------------------------------------------------------------------
#define Hh   2048
#define Kk   16
#define NQ   18          // K + 2
#define NHh  4
#define HD   512         // H / NH
#define FFN  4096        // 2*H
#define MAXE 128
#define Bb   4
#define Ss   4096
#define QH   72          // NQ * NH
#define BS   16384       // B * S
#define EPSf 1e-6f

// Output layout (float32, concatenated in return order)
constexpr long OFF_MEM  = 0;                       // (4,16,2048)
constexpr long OFF_PRI  = 131072;                  // (4,16)
constexpr long OFF_CONF = 131136;                  // (4,)
constexpr long OFF_VAL  = 131140;                  // (4,)
constexpr long OFF_ENT  = 131144;                  // (128,2048)
constexpr long OFF_NPRI = 393288;                  // (128,)

// Scratch arena (floats). [0, ZERO_END) zeroed each call (split-K atomic targets).
constexpr long OFF_QPROJ   = 0;         // 18*2048    = 36864
constexpr long OFF_SCORES  = 36864;     // 72*16384   = 1179648 (attn in place)
constexpr long OFF_CTX     = 1216512;   // 288*2048   = 589824
constexpr long OFF_OUTATTN = 1806336;   // 72*2048    = 147456
constexpr long OFF_EXTR    = 1953792;   // 72*2048    = 147456
constexpr long OFF_GBUF    = 2101248;   // 64*4096    = 262144
constexpr long OFF_UBUF    = 2363392;   // 64*4096    = 262144
constexpr long OFF_FBUF    = 2625536;   // 64*2048    = 131072
constexpr long OFF_H1PRE   = 2756608;   // 4*2048     = 8192
constexpr long OFF_H2PRE   = 2764800;   // 4*512      = 2048
constexpr long ZERO_END    = 2766848;
constexpr long OFF_AMAT    = 2766848;   // 72*2048    = 147456
constexpr long OFF_XN      = 2914304;   // 64*2048    = 131072
constexpr long OFF_TBUF    = 3045376;   // 64*4096    = 262144
constexpr long OFF_VI      = 3307520;   // 4*4096     = 16384
constexpr long OFF_H1      = 3323904;   // 4*2048     = 8192
constexpr long OFF_H2      = 3332096;   // 4*512      = 2048
constexpr long SCRATCH_SZ  = 3334144;

__device__ __align__(256) float g_scratch[SCRATCH_SZ];

// ---------------------------------------------------------------------------
// Packed f32x2 helpers (Blackwell FFMA2: 2 FMAs per issue slot)
// ---------------------------------------------------------------------------
__device__ __forceinline__ unsigned long long pack2(float x) {
    unsigned long long r;
    asm("mov.b64 %0, {%1, %1};" : "=l"(r) : "f"(x));
    return r;
}
__device__ __forceinline__ void ffma2(unsigned long long& d,
                                      unsigned long long a,
                                      unsigned long long b) {
    asm("fma.rn.f32x2 %0, %1, %2, %3;" : "=l"(d) : "l"(a), "l"(b), "l"(d));
}
__device__ __forceinline__ float2 unpack2(unsigned long long v) {
    float2 f;
    asm("mov.b64 {%0, %1}, %2;" : "=f"(f.x), "=f"(f.y) : "l"(v));
    return f;
}

// ---------------------------------------------------------------------------
// Tiled GEMM with packed f32x2 inner loop.
//   C[M,N] (+)= alpha * A[M,K] * op(B)
//   TRANSB=true : B stored [N,K] ; TRANSB=false: B stored [K,N]
// Thread shape: TX x TY (TY=256/TX). Tile: BM=TY*TM, BN=TX*2*TN2, BK=32.
// grid.z = batch * ksplit; ksplit>1 => atomicAdd into pre-zeroed C.
// ---------------------------------------------------------------------------
template<int TM, int TN2, int TX, bool TRANSB>
__global__ __launch_bounds__(256)
void gemm2_k(const float* __restrict__ A, const float* __restrict__ B,
             float* __restrict__ C,
             int M, int N, int K, int lda, int ldb, int ldc,
             long aB, long bB, long cB, int ksplit, float alpha)
{
    constexpr int TY = 256 / TX;
    constexpr int TN = 2 * TN2;
    constexpr int BM = TY * TM;
    constexpr int BN = TX * TN;
    constexpr int BK = 32;
    __shared__ float As[BK][BM + 4];
    __shared__ float Bs[BK][BN + 4];

    const int tid   = threadIdx.x;
    const int batch = blockIdx.z / ksplit;
    const int ks    = blockIdx.z % ksplit;
    A += batch * aB; B += batch * bB; C += batch * cB;

    const int kLen = K / ksplit;
    const int k0   = ks * kLen;
    const int m0   = blockIdx.y * BM;
    const int n0   = blockIdx.x * BN;
    const int tx   = tid % TX, ty = tid / TX;

    unsigned long long acc[TM][TN2];
#pragma unroll
    for (int i = 0; i < TM; i++)
#pragma unroll
        for (int j = 0; j < TN2; j++) acc[i][j] = 0ULL;

    for (int kt = 0; kt < kLen; kt += BK) {
        const int kbase = k0 + kt;
        // A tile (BM x 32), transposed store As[k][m], float4 global loads
#pragma unroll
        for (int idx = tid; idx < BM * 8; idx += 256) {
            int r = idx >> 3, c4 = idx & 7;
            int m = m0 + r;
            float4 v = make_float4(0.f, 0.f, 0.f, 0.f);
            if (m < M) v = *reinterpret_cast<const float4*>(&A[(long)m * lda + kbase + c4 * 4]);
            As[c4 * 4 + 0][r] = v.x;
            As[c4 * 4 + 1][r] = v.y;
            As[c4 * 4 + 2][r] = v.z;
            As[c4 * 4 + 3][r] = v.w;
        }
        if (TRANSB) {
#pragma unroll
            for (int idx = tid; idx < BN * 8; idx += 256) {
                int r = idx >> 3, c4 = idx & 7;
                int n = n0 + r;
                float4 v = make_float4(0.f, 0.f, 0.f, 0.f);
                if (n < N) v = *reinterpret_cast<const float4*>(&B[(long)n * ldb + kbase + c4 * 4]);
                Bs[c4 * 4 + 0][r] = v.x;
                Bs[c4 * 4 + 1][r] = v.y;
                Bs[c4 * 4 + 2][r] = v.z;
                Bs[c4 * 4 + 3][r] = v.w;
            }
        } else {
            constexpr int BN4 = BN / 4;
#pragma unroll
            for (int idx = tid; idx < BK * BN4; idx += 256) {
                int r = idx / BN4, c4 = idx % BN4;
                int n = n0 + c4 * 4;
                float4 v = make_float4(0.f, 0.f, 0.f, 0.f);
                if (n < N) v = *reinterpret_cast<const float4*>(&B[(long)(kbase + r) * ldb + n]);
                *reinterpret_cast<float4*>(&Bs[r][c4 * 4]) = v;
            }
        }
        __syncthreads();
#pragma unroll
        for (int kk = 0; kk < BK; kk++) {
            unsigned long long a2[TM], b2[TN2];
#pragma unroll
            for (int i = 0; i < TM; i++) a2[i] = pack2(As[kk][ty * TM + i]);
#pragma unroll
            for (int j = 0; j < TN2; j++)
                b2[j] = *reinterpret_cast<const unsigned long long*>(&Bs[kk][tx * TN + 2 * j]);
#pragma unroll
            for (int i = 0; i < TM; i++)
#pragma unroll
                for (int j = 0; j < TN2; j++)
                    ffma2(acc[i][j], a2[i], b2[j]);
        }
        __syncthreads();
    }

#pragma unroll
    for (int i = 0; i < TM; i++) {
        int m = m0 + ty * TM + i;
        if (m >= M) continue;
#pragma unroll
        for (int j = 0; j < TN2; j++) {
            int n = n0 + tx * TN + 2 * j;
            if (n >= N) continue;   // N always even -> n+1 < N too
            float2 v = unpack2(acc[i][j]);
            v.x *= alpha; v.y *= alpha;
            float* cp = &C[(long)m * ldc + n];
            if (ksplit > 1) { atomicAdd(cp, v.x); atomicAdd(cp + 1, v.y); }
            else            { cp[0] = v.x; cp[1] = v.y; }
        }
    }
}

// ---------------------------------------------------------------------------
// Elementwise / reduction kernels
// ---------------------------------------------------------------------------
__global__ void zero4_k(float4* p, int n4)
{
    int i = blockIdx.x * blockDim.x + threadIdx.x;
    if (i < n4) p[i] = make_float4(0.f, 0.f, 0.f, 0.f);
}

__device__ __forceinline__ float blockReduceSum(float v, float* sm)
{
    int t = threadIdx.x;
    __syncthreads();
    sm[t] = v; __syncthreads();
    for (int o = blockDim.x >> 1; o > 0; o >>= 1) {
        if (t < o) sm[t] += sm[t + o];
        __syncthreads();
    }
    return sm[0];
}

__device__ __forceinline__ float blockReduceMax(float v, float* sm)
{
    int t = threadIdx.x;
    __syncthreads();
    sm[t] = v; __syncthreads();
    for (int o = blockDim.x >> 1; o > 0; o >>= 1) {
        if (t < o) sm[t] = fmaxf(sm[t], sm[t + o]);
        __syncthreads();
    }
    return sm[0];
}

// In-place softmax over contiguous 4096-row of scores_T[qh][b*4096 ..]
__global__ void softmax_k()
{
    __shared__ float sm[256];
    int b  = blockIdx.x / QH;
    int qh = blockIdx.x % QH;
    float4* r4 = reinterpret_cast<float4*>(
        g_scratch + OFF_SCORES + (long)qh * BS + (long)b * Ss);
    int t = threadIdx.x;

    float mx = -1e30f;
    for (int i = t; i < Ss / 4; i += 256) {
        float4 v = r4[i];
        mx = fmaxf(mx, fmaxf(fmaxf(v.x, v.y), fmaxf(v.z, v.w)));
    }
    mx = blockReduceMax(mx, sm);

    float sum = 0.f;
    for (int i = t; i < Ss / 4; i += 256) {
        float4 v = r4[i];
        v.x = expf(v.x - mx); v.y = expf(v.y - mx);
        v.z = expf(v.z - mx); v.w = expf(v.w - mx);
        r4[i] = v;
        sum += v.x + v.y + v.z + v.w;
    }
    sum = blockReduceSum(sum, sm);
    float inv = 1.f / sum;
    for (int i = t; i < Ss / 4; i += 256) {
        float4 v = r4[i];
        v.x *= inv; v.y *= inv; v.z *= inv; v.w *= inv;
        r4[i] = v;
    }
}

// RMSNorm of extracted rows (b*18+q), q<16 -> xn rows (b*16+q)
__global__ void rms_k(const float* __restrict__ ln_w)
{
    __shared__ float sm[256];
    int b = blockIdx.x >> 4, q = blockIdx.x & 15;
    const float* x = g_scratch + OFF_EXTR + (long)(b * NQ + q) * Hh;
    float* xo      = g_scratch + OFF_XN   + (long)(b * Kk + q) * Hh;
    int t = threadIdx.x;
    float s = 0.f;
    for (int j = t; j < Hh; j += 256) { float v = x[j]; s += v * v; }
    s = blockReduceSum(s, sm);
    float scale = rsqrtf(s / (float)Hh + EPSf);
    for (int j = t; j < Hh; j += 256) xo[j] = x[j] * scale * ln_w[j];
}

__global__ void silu_mul_k(int n)
{
    int i = blockIdx.x * blockDim.x + threadIdx.x;
    if (i < n) {
        float g = g_scratch[OFF_GBUF + i];
        float u = g_scratch[OFF_UBUF + i];
        float s = 1.f / (1.f + expf(-g));
        g_scratch[OFF_TBUF + i] = g * s * u;
    }
}

__global__ void bias_silu_k(long pre_off, const float* __restrict__ bias,
                            long out_off, int n, int bdim)
{
    int i = blockIdx.x * blockDim.x + threadIdx.x;
    if (i < n) {
        float v = g_scratch[pre_off + i] + bias[i % bdim];
        float s = 1.f / (1.f + expf(-v));
        g_scratch[out_off + i] = v * s;
    }
}

__global__ void mem_pri_k(const float* __restrict__ Wp,
                          const float* __restrict__ bp,
                          float* __restrict__ OUT)
{
    __shared__ float sm[256];
    int b = blockIdx.x >> 4, i = blockIdx.x & 15;
    const float* ex = g_scratch + OFF_EXTR + (long)(b * NQ + i) * Hh;
    const float* fb = g_scratch + OFF_FBUF + (long)(b * Kk + i) * Hh;
    float* mo = OUT + OFF_MEM + (long)(b * Kk + i) * Hh;
    int t = threadIdx.x;
    float dot = 0.f;
    for (int j = t; j < Hh; j += 256) {
        float m = ex[j] + fb[j];
        mo[j] = m;
        dot += m * Wp[j];
    }
    dot = blockReduceSum(dot, sm);
    if (t == 0) OUT[OFF_PRI + b * Kk + i] = 1.f / (1.f + expf(-(dot + bp[0])));
}

__global__ void conf_k(const float* __restrict__ Wh,
                       const float* __restrict__ bh,
                       float* __restrict__ OUT)
{
    __shared__ float sm[256];
    int b = blockIdx.x;
    const float* cv = g_scratch + OFF_EXTR + (long)(b * NQ + Kk) * Hh;
    int t = threadIdx.x;
    float dot = 0.f;
    for (int j = t; j < Hh; j += 256) dot += cv[j] * Wh[j];
    dot = blockReduceSum(dot, sm);
    if (t == 0) OUT[OFF_CONF + b] = 1.f / (1.f + expf(-(dot + bh[0])));
}

__global__ void vi_k(const float* __restrict__ hidden)
{
    int b = blockIdx.x;
    const float* vv = g_scratch + OFF_EXTR + (long)(b * NQ + Kk + 1) * Hh;
    const float* hl = hidden + ((long)b * Ss + (Ss - 1)) * Hh;
    float* vi = g_scratch + OFF_VI + (long)b * (2 * Hh);
    for (int j = threadIdx.x; j < 2 * Hh; j += 256)
        vi[j] = (j < Hh) ? vv[j] : hl[j - Hh];
}

__global__ void value_k(const float* __restrict__ V3,
                        const float* __restrict__ b3,
                        float* __restrict__ OUT)
{
    __shared__ float sm[256];
    int b = blockIdx.x;
    const float* h2 = g_scratch + OFF_H2 + (long)b * (Hh / 4);
    int t = threadIdx.x;
    float dot = 0.f;
    for (int j = t; j < Hh / 4; j += 256) dot += h2[j] * V3[j];
    dot = blockReduceSum(dot, sm);
    if (t == 0) OUT[OFF_VAL + b] = dot + b3[0];
}

__global__ void copy_ent_k(const float* __restrict__ src, float* __restrict__ OUT)
{
    long i = (long)blockIdx.x * blockDim.x + threadIdx.x;
    if (i < (long)MAXE * Hh) OUT[OFF_ENT + i] = src[i];
}

// Sequential buffer-update scan (first-index argmin to match jnp.argmin).
__global__ void scan_k(const float* __restrict__ buf_pri, float* __restrict__ OUT)
{
    __shared__ float pr[MAXE];
    __shared__ float sval[MAXE];
    __shared__ int   sidx[MAXE];
    int t = threadIdx.x;           // 128 threads
    pr[t] = buf_pri[t];
    __syncthreads();

    for (int i = 0; i < Kk; i++) {
        sval[t] = pr[t]; sidx[t] = t;
        __syncthreads();
        for (int o = MAXE >> 1; o > 0; o >>= 1) {
            if (t < o) {
                float v2 = sval[t + o]; int i2 = sidx[t + o];
                if (v2 < sval[t] || (v2 == sval[t] && i2 < sidx[t])) {
                    sval[t] = v2; sidx[t] = i2;
                }
            }
            __syncthreads();
        }
        int   idx  = sidx[0];
        float minv = sval[0];
        float p    = OUT[OFF_PRI + i];
        if (p > minv) {
            for (int j = t; j < Hh; j += MAXE)
                OUT[OFF_ENT + (long)idx * Hh + j] = OUT[OFF_MEM + (long)i * Hh + j];
            if (t == 0) pr[idx] = p;
        }
        __syncthreads();
    }
    OUT[OFF_NPRI + t] = pr[t];
}

// ---------------------------------------------------------------------------
// Launch sequence
// ---------------------------------------------------------------------------
extern "C" void kernel_launch(void* const* d_in, const int* in_sizes, int n_in,
                              void* d_out, int out_size)
{
    const float* hidden  = (const float*)d_in[0];
    const float* bufent  = (const float*)d_in[1];
    const float* bufpri  = (const float*)d_in[2];
    const float* queries = (const float*)d_in[3];
    const float* Wq      = (const float*)d_in[4];
    const float* Wk      = (const float*)d_in[5];
    const float* Wv      = (const float*)d_in[6];
    const float* Wo      = (const float*)d_in[7];
    const float* ln_w    = (const float*)d_in[8];
    const float* Wgate   = (const float*)d_in[9];
    const float* Wup     = (const float*)d_in[10];
    const float* Wdown   = (const float*)d_in[11];
    const float* Wp      = (const float*)d_in[12];
    const float* bp      = (const float*)d_in[13];
    const float* Wh      = (const float*)d_in[14];
    const float* bh      = (const float*)d_in[15];
    const float* V1      = (const float*)d_in[16];
    const float* b1      = (const float*)d_in[17];
    const float* V2      = (const float*)d_in[18];
    const float* b2      = (const float*)d_in[19];
    const float* V3      = (const float*)d_in[20];
    const float* b3      = (const float*)d_in[21];
    float* OUT = (float*)d_out;

    float* scr = nullptr;
    cudaGetSymbolAddress((void**)&scr, g_scratch);

    const float inv_sqrt_hd = 0.044194173824159216f;   // 1/sqrt(512)

    // 0) zero split-K atomic targets
    {
        int n4 = (int)(ZERO_END / 4);
        zero4_k<<<(n4 + 255) / 256, 256>>>((float4*)scr, n4);
    }

    // 1) q_proj = queries @ Wq^T : (18, 2048), ks=4
    gemm2_k<2,5,16,true><<<dim3(13,1,4), 256>>>(queries, Wq, scr + OFF_QPROJ,
        18, 2048, 2048, 2048, 2048, 2048, 0, 0, 0, 4, 1.f);

    // 2) AMAT[qh=q*4+h] = q_proj[q, h*512:] @ Wk[h*512:, :] * 1/sqrt(HD)
    //    batched over 4 heads (z=4, ks=1); C interleaved: row = 4m+h via ldc/cB
    gemm2_k<2,5,16,false><<<dim3(13,1,4), 256>>>(scr + OFF_QPROJ, Wk, scr + OFF_AMAT,
        18, 2048, 512, 2048, 2048, 4*2048,
        512, (long)512*2048, 2048, 1, inv_sqrt_hd);

    // 3) scores_T[qh, bs] = AMAT @ hidden^T : (72, 16384), ks=2
    gemm2_k<5,5,16,true><<<dim3(103,1,2), 256>>>(scr + OFF_AMAT, hidden, scr + OFF_SCORES,
        72, BS, 2048, 2048, 2048, BS, 0, 0, 0, 2, 1.f);

    // 4) softmax in place over each (b, qh) 4096-row
    softmax_k<<<Bb * QH, 256>>>();

    // 5) ctx[b*72+qh, :] = attn[b] @ hidden[b] : (72, 2048) x4 batches, ks=4
    gemm2_k<5,5,16,false><<<dim3(13,1,16), 256>>>(scr + OFF_SCORES, hidden, scr + OFF_CTX,
        72, 2048, 4096, BS, 2048, 2048,
        4096, (long)4096*2048, (long)72*2048, 4, 1.f);

    // 6) out_attn[b*18+q, h*512+d] = ctx[(b,q,h)] @ Wv_h^T : 4 head batches, ks=4
    gemm2_k<5,5,16,true><<<dim3(4,1,16), 256>>>(scr + OFF_CTX, Wv, scr + OFF_OUTATTN,
        72, 512, 2048, 4*2048, 2048, 2048,
        2048, (long)512*2048, 512, 4, 1.f);

    // 7) extracted = out_attn @ Wo^T : (72, 2048), ks=8
    gemm2_k<5,5,16,true><<<dim3(13,1,8), 256>>>(scr + OFF_OUTATTN, Wo, scr + OFF_EXTR,
        72, 2048, 2048, 2048, 2048, 2048, 0, 0, 0, 8, 1.f);

    // 8) RMSNorm -> xn (64, 2048)
    rms_k<<<64, 256>>>(ln_w);

    // 9) gate / up : (64, 4096), ks=4
    gemm2_k<4,5,16,true><<<dim3(26,1,4), 256>>>(scr + OFF_XN, Wgate, scr + OFF_GBUF,
        64, 4096, 2048, 2048, 2048, 4096, 0, 0, 0, 4, 1.f);
    gemm2_k<4,5,16,true><<<dim3(26,1,4), 256>>>(scr + OFF_XN, Wup, scr + OFF_UBUF,
        64, 4096, 2048, 2048, 2048, 4096, 0, 0, 0, 4, 1.f);

    // 10) t = silu(gate) * up
    silu_mul_k<<<(64*4096 + 255) / 256, 256>>>(64 * 4096);

    // 11) ffn = t @ Wdown^T : (64, 2048), ks=8
    gemm2_k<4,5,16,true><<<dim3(13,1,8), 256>>>(scr + OFF_TBUF, Wdown, scr + OFF_FBUF,
        64, 2048, 4096, 4096, 4096, 2048, 0, 0, 0, 8, 1.f);

    // 12) memory (to OUT) + priority
    mem_pri_k<<<64, 256>>>(Wp, bp, OUT);

    // 13) confidence
    conf_k<<<4, 256>>>(Wh, bh, OUT);

    // 14) value head
    vi_k<<<4, 256>>>(hidden);
    gemm2_k<1,5,16,true><<<dim3(13,1,8), 256>>>(scr + OFF_VI, V1, scr + OFF_H1PRE,
        4, 2048, 4096, 4096, 4096, 2048, 0, 0, 0, 8, 1.f);
    bias_silu_k<<<(4*2048 + 255) / 256, 256>>>(OFF_H1PRE, b1, OFF_H1, 4*2048, 2048);
    gemm2_k<1,5,16,true><<<dim3(4,1,4), 256>>>(scr + OFF_H1, V2, scr + OFF_H2PRE,
        4, 512, 2048, 2048, 2048, 512, 0, 0, 0, 4, 1.f);
    bias_silu_k<<<(4*512 + 255) / 256, 256>>>(OFF_H2PRE, b2, OFF_H2, 4*512, 512);
    value_k<<<4, 256>>>(V3, b3, OUT);

    // 15) buffer update: copy entries, then sequential scan
    copy_ent_k<<<(MAXE*Hh + 255) / 256, 256>>>(bufent, OUT);
    scan_k<<<1, MAXE>>>(bufpri, OUT);
}